// round 12
// baseline (speedup 1.0000x reference)
#include <cuda_runtime.h>
#include <cuda_fp16.h>
#include <cstdint>

// Problem shapes (fixed by the dataset)
constexpr int M_TOK = 16384;   // b*s
constexpr int KDIM  = 2048;    // h
constexpr int NTOT  = 192;     // q|k|v

// GEMM tiling — BM=64, BK=64, 256 threads (8 warps: 2x4), 2 CTAs/SM
constexpr int BM = 64;
constexpr int BN = 192;
constexpr int BK = 64;
constexpr int PAD_K = 72;      // row = 144 B (16B-aligned; LDSM conflict-free)
constexpr int NCHUNK = KDIM / BK;  // 32

constexpr int SM_X = BM * PAD_K;   // 4608 fp16 = 9216 B
constexpr int SM_W = BN * PAD_K;   // 13824 fp16 = 27648 B

constexpr int XBUF_STRIDE_B = SM_X * 2;           // 9216 B
constexpr int WBUF_STRIDE_B = SM_W * 2;           // 27648 B
constexpr int OFF_X_B = 0;
constexpr int OFF_W_B = 2 * XBUF_STRIDE_B;        // 18432
// X double-buffered, W TRIPLE-buffered
constexpr int SMEM_BYTES = 2 * XBUF_STRIDE_B + 3 * WBUF_STRIDE_B;  // 101376 B

// Scratch
__device__ __half g_Wt[(size_t)NTOT * KDIM];      // [n][k], fp16
__device__ float g_qkv[(size_t)M_TOK * NTOT];

// ---------------------------------------------------------------- helpers
__device__ __forceinline__ void mma16816(float (&c)[4], const uint32_t (&a)[4],
                                         uint32_t b0, uint32_t b1) {
    asm volatile(
        "mma.sync.aligned.m16n8k16.row.col.f32.f16.f16.f32 "
        "{%0,%1,%2,%3}, {%4,%5,%6,%7}, {%8,%9}, {%0,%1,%2,%3};\n"
        : "+f"(c[0]), "+f"(c[1]), "+f"(c[2]), "+f"(c[3])
        : "r"(a[0]), "r"(a[1]), "r"(a[2]), "r"(a[3]), "r"(b0), "r"(b1));
}
__device__ __forceinline__ void ldsm4(uint32_t (&r)[4], uint32_t addr) {
    asm volatile("ldmatrix.sync.aligned.m8n8.x4.shared.b16 {%0,%1,%2,%3}, [%4];"
                 : "=r"(r[0]), "=r"(r[1]), "=r"(r[2]), "=r"(r[3]) : "r"(addr));
}
__device__ __forceinline__ void cp_async16(uint32_t dst, const void* src) {
    asm volatile("cp.async.cg.shared.global [%0], [%1], 16;\n" :: "r"(dst), "l"(src) : "memory");
}
__device__ __forceinline__ void cp_commit() {
    asm volatile("cp.async.commit_group;\n" ::: "memory");
}
__device__ __forceinline__ uint32_t cvt_f16x2(float a, float b) {  // pack (a lo, b hi)
    uint32_t r;
    asm("cvt.rn.f16x2.f32 %0, %1, %2;" : "=r"(r) : "f"(b), "f"(a));
    return r;
}
__device__ __forceinline__ float ex2f(float x) {
    float y;
    asm("ex2.approx.ftz.f32 %0, %1;" : "=f"(y) : "f"(x));
    return y;
}
// exp2 on the FMA/ALU pipes (deg-4 poly, rel err ~1e-6). |t| < 2^21 assumed.
__device__ __forceinline__ float exp2_poly(float t) {
    const float C = 12582912.0f;               // 2^23 + 2^22
    float big = t + C;                          // round(t) captured in mantissa
    int   i   = __float_as_int(big);
    float n   = big - C;                        // nearest integer to t
    float f   = t - n;                          // f in [-0.5, 0.5]
    float p   = 0.0096181291f;
    p = fmaf(p, f, 0.0555041087f);
    p = fmaf(p, f, 0.2402264579f);
    p = fmaf(p, f, 0.6931471825f);
    p = fmaf(p, f, 1.0f);
    float sc = __int_as_float((i << 23) + 0x3F800000);   // 2^n
    return sc * p;
}

// ---------------------------------------------------------------- prep_w v3
// No smem, no sync. Block b handles output row n=b (z = b&63 of matrix b>>6).
// Thread kq loads 8 k-values down column z (MLP=8, 256B stride, L2-shared
// across blocks), converts, writes one coalesced uint4 to g_Wt[n][kq*8].
__global__ void __launch_bounds__(256)
prep_w(const float* __restrict__ Wq,
       const float* __restrict__ Wk,
       const float* __restrict__ Wv) {
    const int n = blockIdx.x;                 // 0..191
    const int m = n >> 6;
    const int z = n & 63;
    const float* W = (m == 0) ? Wq : ((m == 1) ? Wk : Wv);
    const int kq = threadIdx.x;               // 0..255
    const int k0 = kq * 8;

    float w[8];
#pragma unroll
    for (int j = 0; j < 8; j++)
        w[j] = W[(size_t)(k0 + j) * 64 + z];

    uint32_t p[4];
#pragma unroll
    for (int j = 0; j < 4; j++)
        p[j] = cvt_f16x2(w[2 * j], w[2 * j + 1]);

    *reinterpret_cast<uint4*>(&g_Wt[(size_t)n * KDIM + k0]) =
        make_uint4(p[0], p[1], p[2], p[3]);
}

// ---------------------------------------------------------------- QKV GEMM
// BK=64, triple-buffered W with wait_group 1 (cp.async fully hidden).
__global__ void __launch_bounds__(256, 2)
qkv_gemm(const float* __restrict__ X) {
    extern __shared__ __half smem[];
    const uint32_t sbase = (uint32_t)__cvta_generic_to_shared(smem);

    const int tid  = threadIdx.x;
    const int lane = tid & 31;
    const int wid  = tid >> 5;
    const int g    = lane >> 2;
    const int tig  = lane & 3;
    const int warp_m = (wid & 1) * 32;     // 2 warp rows of 32
    const int warp_n = (wid >> 1) * 48;    // 4 warp cols of 48
    const int m0 = blockIdx.x * BM;

    const int lrow = lane & 7;
    const int lbit3 = (lane >> 3) & 1;
    const int lbit4 = (lane >> 4) & 1;

    uint32_t aA[2];
#pragma unroll
    for (int mt = 0; mt < 2; mt++) {
        int row = warp_m + mt * 16 + lrow + lbit3 * 8;
        aA[mt] = sbase + OFF_X_B + (uint32_t)row * 144u + (uint32_t)lbit4 * 16u;
    }
    uint32_t bA[3];
#pragma unroll
    for (int p = 0; p < 3; p++) {
        int row = warp_n + p * 16 + lrow + lbit4 * 8;
        bA[p] = sbase + OFF_W_B + (uint32_t)row * 144u + (uint32_t)lbit3 * 16u;
    }

    // X: 4 threads/row
    const int xr = tid >> 2;               // 0..63
    const int xq = tid & 3;
    const uint32_t xsts = sbase + OFF_X_B + (uint32_t)xr * 144u + (uint32_t)xq * 16u;
    const float* xsrc_row = X + (size_t)(m0 + xr) * KDIM + xq * 8;

    const uint32_t wdst0 = sbase + OFF_W_B;

    float acc[2][6][4];
#pragma unroll
    for (int mt = 0; mt < 2; mt++)
#pragma unroll
        for (int nt = 0; nt < 6; nt++)
#pragma unroll
            for (int r = 0; r < 4; r++) acc[mt][nt][r] = 0.f;

    float4 xf[2];

    auto convert_sts = [&](uint32_t dOff, int h) {
        uint32_t hw[4];
        hw[0] = cvt_f16x2(xf[0].x, xf[0].y);
        hw[1] = cvt_f16x2(xf[0].z, xf[0].w);
        hw[2] = cvt_f16x2(xf[1].x, xf[1].y);
        hw[3] = cvt_f16x2(xf[1].z, xf[1].w);
        asm volatile("st.shared.v4.b32 [%0], {%1,%2,%3,%4};" ::
                     "r"(xsts + dOff + (uint32_t)h * 64u),
                     "r"(hw[0]), "r"(hw[1]), "r"(hw[2]), "r"(hw[3]));
    };

    auto ldg_x = [&](int c, int h) {
        const float4* p = reinterpret_cast<const float4*>(
            xsrc_row + (size_t)c * BK + h * 32);
        xf[0] = p[0]; xf[1] = p[1];
    };

    auto issue_w = [&](int c, uint32_t dOff) {
        const size_t koff = (size_t)c * BK;
#pragma unroll
        for (int r = 0; r < 6; r++) {
            int u = tid + r * 256;
            int n = u >> 3, q = u & 7;
            uint32_t d = wdst0 + dOff + (uint32_t)n * 144u + (uint32_t)q * 16u;
            cp_async16(d, g_Wt + (size_t)n * KDIM + koff + q * 8);
        }
        cp_commit();
    };

    // --- prologue ---
    issue_w(0, 0);
    issue_w(1, WBUF_STRIDE_B);
    ldg_x(0, 0); convert_sts(0, 0);
    ldg_x(0, 1); convert_sts(0, 1);
    ldg_x(1, 0);
    asm volatile("cp.async.wait_group 1;\n" ::: "memory");   // W(0) landed
    __syncthreads();

    uint32_t wCur = 0, wNext = WBUF_STRIDE_B, wFill = 2u * WBUF_STRIDE_B;

#pragma unroll 1
    for (int c = 0; c < NCHUNK; ++c) {
        const uint32_t xOff  = (uint32_t)(c & 1) * XBUF_STRIDE_B;
        const uint32_t xNext = (uint32_t)((c + 1) & 1) * XBUF_STRIDE_B;

        if (c + 1 < NCHUNK) {
            convert_sts(xNext, 0);
            ldg_x(c + 1, 1);
        }
        if (c + 2 < NCHUNK) issue_w(c + 2, wFill);

#pragma unroll
        for (int kk2 = 0; kk2 < 2; kk2++) {
            const uint32_t kb = kk2 * 32;
            uint32_t ah[2][4], bh[3][4];
#pragma unroll
            for (int mt = 0; mt < 2; mt++) ldsm4(ah[mt], aA[mt] + xOff + kb);
#pragma unroll
            for (int p = 0; p < 3; p++)    ldsm4(bh[p], bA[p] + wCur + kb);
#pragma unroll
            for (int mt = 0; mt < 2; mt++)
#pragma unroll
                for (int nt = 0; nt < 6; nt++)
                    mma16816(acc[mt][nt], ah[mt],
                             bh[nt >> 1][(nt & 1) * 2], bh[nt >> 1][(nt & 1) * 2 + 1]);
        }

        if (c + 1 < NCHUNK) {
            convert_sts(xNext, 1);
            if (c + 2 < NCHUNK) ldg_x(c + 2, 0);
        }

#pragma unroll
        for (int kk2 = 2; kk2 < 4; kk2++) {
            const uint32_t kb = kk2 * 32;
            uint32_t ah[2][4], bh[3][4];
#pragma unroll
            for (int mt = 0; mt < 2; mt++) ldsm4(ah[mt], aA[mt] + xOff + kb);
#pragma unroll
            for (int p = 0; p < 3; p++)    ldsm4(bh[p], bA[p] + wCur + kb);
#pragma unroll
            for (int mt = 0; mt < 2; mt++)
#pragma unroll
                for (int nt = 0; nt < 6; nt++)
                    mma16816(acc[mt][nt], ah[mt],
                             bh[nt >> 1][(nt & 1) * 2], bh[nt >> 1][(nt & 1) * 2 + 1]);
        }

        if (c + 1 < NCHUNK) {
            if (c + 2 < NCHUNK) {
                asm volatile("cp.async.wait_group 1;\n" ::: "memory");
            } else {
                asm volatile("cp.async.wait_group 0;\n" ::: "memory");
            }
            __syncthreads();
        }

        uint32_t tmp = wCur; wCur = wNext; wNext = wFill; wFill = tmp;
    }

    // epilogue: write q|k|v to scratch
#pragma unroll
    for (int mt = 0; mt < 2; mt++) {
#pragma unroll
        for (int nt = 0; nt < 6; nt++) {
            int r  = m0 + warp_m + mt * 16 + g;
            int cn = warp_n + nt * 8 + 2 * tig;
            float2 v0 = make_float2(acc[mt][nt][0], acc[mt][nt][1]);
            float2 v1 = make_float2(acc[mt][nt][2], acc[mt][nt][3]);
            *reinterpret_cast<float2*>(&g_qkv[(size_t)r * NTOT + cn]) = v0;
            *reinterpret_cast<float2*>(&g_qkv[(size_t)(r + 8) * NTOT + cn]) = v1;
        }
    }
}

// ---------------------------------------------------------------- attention
// MUFU/FMA hybrid: 3 of 16 j-blocks use poly exp2 (FMA pipe), rest MUFU.
__global__ void __launch_bounds__(256)
attn_kernel(float* __restrict__ out) {
    __shared__ float4 ks[4][16];
    __shared__ float4 vs[4][16];
    const int tid = threadIdx.x;
    const int tl = tid >> 6;
    const int i  = tid & 63;
    const size_t tok = (size_t)blockIdx.x * 4 + tl;
    const float* base = g_qkv + tok * NTOT;

    float q = base[i] * 1.4426950408889634f;   // fold log2(e)
    reinterpret_cast<float*>(&ks[tl][0])[i] = base[64 + i];
    reinterpret_cast<float*>(&vs[tl][0])[i] = base[128 + i];
    __syncthreads();

    float s = 0.f, num = 0.f;
#pragma unroll
    for (int j4 = 0; j4 < 16; j4++) {
        float4 k4 = ks[tl][j4];
        float4 v4 = vs[tl][j4];
        float e0, e1, e2, e3;
        if (j4 == 4 || j4 == 9 || j4 == 14) {   // FMA-pipe exps
            e0 = exp2_poly(q * k4.x);
            e1 = exp2_poly(q * k4.y);
            e2 = exp2_poly(q * k4.z);
            e3 = exp2_poly(q * k4.w);
        } else {                                 // MUFU exps
            e0 = ex2f(q * k4.x);
            e1 = ex2f(q * k4.y);
            e2 = ex2f(q * k4.z);
            e3 = ex2f(q * k4.w);
        }
        s += (e0 + e1) + (e2 + e3);
        num = fmaf(e0, v4.x, num);
        num = fmaf(e1, v4.y, num);
        num = fmaf(e2, v4.z, num);
        num = fmaf(e3, v4.w, num);
    }
    out[tok * 64 + i] = num / s;
}

// ----------------------------------------------------------------
extern "C" void kernel_launch(void* const* d_in, const int* in_sizes, int n_in,
                              void* d_out, int out_size) {
    const float* X  = (const float*)d_in[0];
    const float* Wq = (const float*)d_in[1];
    const float* Wk = (const float*)d_in[2];
    const float* Wv = (const float*)d_in[3];
    float* out = (float*)d_out;

    cudaFuncSetAttribute(qkv_gemm, cudaFuncAttributeMaxDynamicSharedMemorySize,
                         SMEM_BYTES);

    prep_w<<<192, 256>>>(Wq, Wk, Wv);
    qkv_gemm<<<M_TOK / BM, 256, SMEM_BYTES>>>(X);
    attn_kernel<<<M_TOK / 4, 256>>>(out);
}

// round 13
// speedup vs baseline: 1.0581x; 1.0581x over previous
#include <cuda_runtime.h>
#include <cuda_fp16.h>
#include <cstdint>

// Problem shapes (fixed by the dataset)
constexpr int M_TOK = 16384;   // b*s
constexpr int KDIM  = 2048;    // h
constexpr int NTOT  = 192;     // q|k|v

// GEMM tiling — BM=64, BK=64, 256 threads (8 warps: 2x4), 2 CTAs/SM
constexpr int BM = 64;
constexpr int BN = 192;
constexpr int BK = 64;
constexpr int PAD_K = 72;      // row = 144 B (16B-aligned; LDSM conflict-free)
constexpr int NCHUNK = KDIM / BK;  // 32

constexpr int SM_X = BM * PAD_K;   // 4608 fp16 = 9216 B
constexpr int SM_W = BN * PAD_K;   // 13824 fp16 = 27648 B

constexpr int XBUF_STRIDE_B = SM_X * 2;           // 9216 B
constexpr int WBUF_STRIDE_B = SM_W * 2;           // 27648 B
constexpr int OFF_X_B = 0;
constexpr int OFF_W_B = 2 * XBUF_STRIDE_B;        // 18432
// X double-buffered, W TRIPLE-buffered
constexpr int SMEM_BYTES = 2 * XBUF_STRIDE_B + 3 * WBUF_STRIDE_B;  // 101376 B

// Scratch
__device__ __half g_Wt[(size_t)NTOT * KDIM];      // [n][k], fp16
__device__ float g_qkv[(size_t)M_TOK * NTOT];

// ---------------------------------------------------------------- helpers
__device__ __forceinline__ void mma16816(float (&c)[4], const uint32_t (&a)[4],
                                         uint32_t b0, uint32_t b1) {
    asm volatile(
        "mma.sync.aligned.m16n8k16.row.col.f32.f16.f16.f32 "
        "{%0,%1,%2,%3}, {%4,%5,%6,%7}, {%8,%9}, {%0,%1,%2,%3};\n"
        : "+f"(c[0]), "+f"(c[1]), "+f"(c[2]), "+f"(c[3])
        : "r"(a[0]), "r"(a[1]), "r"(a[2]), "r"(a[3]), "r"(b0), "r"(b1));
}
__device__ __forceinline__ void ldsm4(uint32_t (&r)[4], uint32_t addr) {
    asm volatile("ldmatrix.sync.aligned.m8n8.x4.shared.b16 {%0,%1,%2,%3}, [%4];"
                 : "=r"(r[0]), "=r"(r[1]), "=r"(r[2]), "=r"(r[3]) : "r"(addr));
}
__device__ __forceinline__ void cp_async16(uint32_t dst, const void* src) {
    asm volatile("cp.async.cg.shared.global [%0], [%1], 16;\n" :: "r"(dst), "l"(src) : "memory");
}
__device__ __forceinline__ void cp_commit() {
    asm volatile("cp.async.commit_group;\n" ::: "memory");
}
__device__ __forceinline__ uint32_t cvt_f16x2(float a, float b) {  // pack (a lo, b hi)
    uint32_t r;
    asm("cvt.rn.f16x2.f32 %0, %1, %2;" : "=r"(r) : "f"(b), "f"(a));
    return r;
}
__device__ __forceinline__ float ex2f(float x) {
    float y;
    asm("ex2.approx.ftz.f32 %0, %1;" : "=f"(y) : "f"(x));
    return y;
}

// ---------------------------------------------------------------- prep_w (v2)
// Vectorized tiled transpose W(h,z) -> Wt[n][k] fp16. 192 blocks x 256 threads.
__global__ void prep_w(const float* __restrict__ Wq,
                       const float* __restrict__ Wk,
                       const float* __restrict__ Wv) {
    __shared__ float s[32][65];
    const int m  = blockIdx.x / 64;          // matrix
    const int k0 = (blockIdx.x % 64) * 32;   // k tile
    const float* W = (m == 0) ? Wq : ((m == 1) ? Wk : Wv);
    const int t = threadIdx.x;

#pragma unroll
    for (int i = 0; i < 2; i++) {
        int u = t + i * 256;                 // float4 index
        int kl = u >> 4, c4 = u & 15;
        float4 v = reinterpret_cast<const float4*>(
            W + (size_t)(k0 + kl) * 64)[c4];
        s[kl][c4 * 4 + 0] = v.x;
        s[kl][c4 * 4 + 1] = v.y;
        s[kl][c4 * 4 + 2] = v.z;
        s[kl][c4 * 4 + 3] = v.w;
    }
    __syncthreads();

    const int z   = t >> 2;
    const int klq = (t & 3) * 8;
    uint32_t p[4];
#pragma unroll
    for (int j = 0; j < 4; j++)
        p[j] = cvt_f16x2(s[klq + 2 * j][z], s[klq + 2 * j + 1][z]);
    size_t o = (size_t)(m * 64 + z) * KDIM + k0 + klq;
    *reinterpret_cast<uint4*>(&g_Wt[o]) = make_uint4(p[0], p[1], p[2], p[3]);
}

// ---------------------------------------------------------------- QKV GEMM
// BK=64, triple-buffered W, register double-buffered fragments.
__global__ void __launch_bounds__(256, 2)
qkv_gemm(const float* __restrict__ X) {
    extern __shared__ __half smem[];
    const uint32_t sbase = (uint32_t)__cvta_generic_to_shared(smem);

    const int tid  = threadIdx.x;
    const int lane = tid & 31;
    const int wid  = tid >> 5;
    const int g    = lane >> 2;
    const int tig  = lane & 3;
    const int warp_m = (wid & 1) * 32;     // 2 warp rows of 32
    const int warp_n = (wid >> 1) * 48;    // 4 warp cols of 48
    const int m0 = blockIdx.x * BM;

    const int lrow = lane & 7;
    const int lbit3 = (lane >> 3) & 1;
    const int lbit4 = (lane >> 4) & 1;

    uint32_t aA[2];
#pragma unroll
    for (int mt = 0; mt < 2; mt++) {
        int row = warp_m + mt * 16 + lrow + lbit3 * 8;
        aA[mt] = sbase + OFF_X_B + (uint32_t)row * 144u + (uint32_t)lbit4 * 16u;
    }
    uint32_t bA[3];
#pragma unroll
    for (int p = 0; p < 3; p++) {
        int row = warp_n + p * 16 + lrow + lbit4 * 8;
        bA[p] = sbase + OFF_W_B + (uint32_t)row * 144u + (uint32_t)lbit3 * 16u;
    }

    // X: 4 threads/row
    const int xr = tid >> 2;               // 0..63
    const int xq = tid & 3;
    const uint32_t xsts = sbase + OFF_X_B + (uint32_t)xr * 144u + (uint32_t)xq * 16u;
    const float* xsrc_row = X + (size_t)(m0 + xr) * KDIM + xq * 8;

    const uint32_t wdst0 = sbase + OFF_W_B;

    float acc[2][6][4];
#pragma unroll
    for (int mt = 0; mt < 2; mt++)
#pragma unroll
        for (int nt = 0; nt < 6; nt++)
#pragma unroll
            for (int r = 0; r < 4; r++) acc[mt][nt][r] = 0.f;

    float4 xf[2];

    auto convert_sts = [&](uint32_t dOff, int h) {
        uint32_t hw[4];
        hw[0] = cvt_f16x2(xf[0].x, xf[0].y);
        hw[1] = cvt_f16x2(xf[0].z, xf[0].w);
        hw[2] = cvt_f16x2(xf[1].x, xf[1].y);
        hw[3] = cvt_f16x2(xf[1].z, xf[1].w);
        asm volatile("st.shared.v4.b32 [%0], {%1,%2,%3,%4};" ::
                     "r"(xsts + dOff + (uint32_t)h * 64u),
                     "r"(hw[0]), "r"(hw[1]), "r"(hw[2]), "r"(hw[3]));
    };

    auto ldg_x = [&](int c, int h) {
        const float4* p = reinterpret_cast<const float4*>(
            xsrc_row + (size_t)c * BK + h * 32);
        xf[0] = p[0]; xf[1] = p[1];
    };

    auto issue_w = [&](int c, uint32_t dOff) {
        const size_t koff = (size_t)c * BK;
#pragma unroll
        for (int r = 0; r < 6; r++) {
            int u = tid + r * 256;
            int n = u >> 3, q = u & 7;
            uint32_t d = wdst0 + dOff + (uint32_t)n * 144u + (uint32_t)q * 16u;
            cp_async16(d, g_Wt + (size_t)n * KDIM + koff + q * 8);
        }
        cp_commit();
    };

    // fragment load / mma helpers (register double buffering)
    uint32_t ahb[2][2][4], bhb[2][3][4];
    auto frag_load = [&](uint32_t xOff, uint32_t wOff, int kk2, int fb) {
        const uint32_t kb = (uint32_t)kk2 * 32u;
#pragma unroll
        for (int mt = 0; mt < 2; mt++) ldsm4(ahb[fb][mt], aA[mt] + xOff + kb);
#pragma unroll
        for (int p = 0; p < 3; p++)    ldsm4(bhb[fb][p], bA[p] + wOff + kb);
    };
    auto do_mma = [&](int fb) {
#pragma unroll
        for (int mt = 0; mt < 2; mt++)
#pragma unroll
            for (int nt = 0; nt < 6; nt++)
                mma16816(acc[mt][nt], ahb[fb][mt],
                         bhb[fb][nt >> 1][(nt & 1) * 2],
                         bhb[fb][nt >> 1][(nt & 1) * 2 + 1]);
    };

    // --- prologue ---
    issue_w(0, 0);
    issue_w(1, WBUF_STRIDE_B);
    ldg_x(0, 0); convert_sts(0, 0);
    ldg_x(0, 1); convert_sts(0, 1);
    ldg_x(1, 0);
    asm volatile("cp.async.wait_group 1;\n" ::: "memory");   // W(0) landed
    __syncthreads();

    uint32_t wCur = 0, wNext = WBUF_STRIDE_B, wFill = 2u * WBUF_STRIDE_B;

#pragma unroll 1
    for (int c = 0; c < NCHUNK; ++c) {
        const uint32_t xOff  = (uint32_t)(c & 1) * XBUF_STRIDE_B;
        const uint32_t xNext = (uint32_t)((c + 1) & 1) * XBUF_STRIDE_B;

        // preload kk2=0 fragments, then staging work
        frag_load(xOff, wCur, 0, 0);
        if (c + 1 < NCHUNK) {
            convert_sts(xNext, 0);
            ldg_x(c + 1, 1);
        }
        if (c + 2 < NCHUNK) issue_w(c + 2, wFill);

        // pipelined: load kk2+1 before issuing kk2's MMAs
        frag_load(xOff, wCur, 1, 1);
        do_mma(0);
        frag_load(xOff, wCur, 2, 0);
        do_mma(1);

        if (c + 1 < NCHUNK) {
            convert_sts(xNext, 1);
            if (c + 2 < NCHUNK) ldg_x(c + 2, 0);
        }

        frag_load(xOff, wCur, 3, 1);
        do_mma(0);
        do_mma(1);

        // tail: W(c+1) landed (issued a full chunk ago); X(c+1) visible
        if (c + 1 < NCHUNK) {
            if (c + 2 < NCHUNK) {
                asm volatile("cp.async.wait_group 1;\n" ::: "memory");
            } else {
                asm volatile("cp.async.wait_group 0;\n" ::: "memory");
            }
            __syncthreads();
        }

        uint32_t tmp = wCur; wCur = wNext; wNext = wFill; wFill = tmp;
    }

    // epilogue: write q|k|v to scratch
#pragma unroll
    for (int mt = 0; mt < 2; mt++) {
#pragma unroll
        for (int nt = 0; nt < 6; nt++) {
            int r  = m0 + warp_m + mt * 16 + g;
            int cn = warp_n + nt * 8 + 2 * tig;
            float2 v0 = make_float2(acc[mt][nt][0], acc[mt][nt][1]);
            float2 v1 = make_float2(acc[mt][nt][2], acc[mt][nt][3]);
            *reinterpret_cast<float2*>(&g_qkv[(size_t)r * NTOT + cn]) = v0;
            *reinterpret_cast<float2*>(&g_qkv[(size_t)(r + 8) * NTOT + cn]) = v1;
        }
    }
}

// ---------------------------------------------------------------- attention
// No max-subtraction (softmax shift-invariant; |q·k| within fp32 exp range).
__global__ void __launch_bounds__(256)
attn_kernel(float* __restrict__ out) {
    __shared__ float4 ks[4][16];
    __shared__ float4 vs[4][16];
    const int tid = threadIdx.x;
    const int tl = tid >> 6;
    const int i  = tid & 63;
    const size_t tok = (size_t)blockIdx.x * 4 + tl;
    const float* base = g_qkv + tok * NTOT;

    float q = base[i] * 1.4426950408889634f;   // fold log2(e)
    reinterpret_cast<float*>(&ks[tl][0])[i] = base[64 + i];
    reinterpret_cast<float*>(&vs[tl][0])[i] = base[128 + i];
    __syncthreads();

    float s = 0.f, num = 0.f;
#pragma unroll
    for (int j4 = 0; j4 < 16; j4++) {
        float4 k4 = ks[tl][j4];
        float4 v4 = vs[tl][j4];
        float e0 = ex2f(q * k4.x);
        float e1 = ex2f(q * k4.y);
        float e2 = ex2f(q * k4.z);
        float e3 = ex2f(q * k4.w);
        s += (e0 + e1) + (e2 + e3);
        num = fmaf(e0, v4.x, num);
        num = fmaf(e1, v4.y, num);
        num = fmaf(e2, v4.z, num);
        num = fmaf(e3, v4.w, num);
    }
    out[tok * 64 + i] = num / s;
}

// ----------------------------------------------------------------
extern "C" void kernel_launch(void* const* d_in, const int* in_sizes, int n_in,
                              void* d_out, int out_size) {
    const float* X  = (const float*)d_in[0];
    const float* Wq = (const float*)d_in[1];
    const float* Wk = (const float*)d_in[2];
    const float* Wv = (const float*)d_in[3];
    float* out = (float*)d_out;

    cudaFuncSetAttribute(qkv_gemm, cudaFuncAttributeMaxDynamicSharedMemorySize,
                         SMEM_BYTES);

    prep_w<<<192, 256>>>(Wq, Wk, Wv);
    qkv_gemm<<<M_TOK / BM, 256, SMEM_BYTES>>>(X);
    attn_kernel<<<M_TOK / 4, 256>>>(out);
}

// round 14
// speedup vs baseline: 1.0803x; 1.0210x over previous
#include <cuda_runtime.h>
#include <cuda_fp16.h>
#include <cstdint>

// Problem shapes (fixed by the dataset)
constexpr int M_TOK = 16384;   // b*s
constexpr int KDIM  = 2048;    // h
constexpr int NTOT  = 192;     // q|k|v

// GEMM tiling — BM=64, BK=64, 256 threads (8 warps: 2x4), 2 CTAs/SM
constexpr int BM = 64;
constexpr int BN = 192;
constexpr int BK = 64;
constexpr int PAD_K = 72;      // row = 144 B (16B-aligned; LDSM conflict-free)
constexpr int NCHUNK = KDIM / BK;  // 32
constexpr int NCTA = M_TOK / BM;   // 256

constexpr int SM_X = BM * PAD_K;   // 4608 fp16 = 9216 B
constexpr int SM_W = BN * PAD_K;   // 13824 fp16 = 27648 B

constexpr int XBUF_STRIDE_B = SM_X * 2;           // 9216 B
constexpr int WBUF_STRIDE_B = SM_W * 2;           // 27648 B
constexpr int OFF_X_B = 0;
constexpr int OFF_W_B = 2 * XBUF_STRIDE_B;        // 18432
// X double-buffered, W TRIPLE-buffered
constexpr int SMEM_BYTES = 2 * XBUF_STRIDE_B + 3 * WBUF_STRIDE_B;  // 101376 B

// Scratch
__device__ __half g_Wt[(size_t)NTOT * KDIM];      // [n][k], fp16
__device__ float g_qkv[(size_t)M_TOK * NTOT];
__device__ unsigned g_count;                      // epoch barrier (monotonic)

// ---------------------------------------------------------------- helpers
__device__ __forceinline__ void mma16816(float (&c)[4], const uint32_t (&a)[4],
                                         uint32_t b0, uint32_t b1) {
    asm volatile(
        "mma.sync.aligned.m16n8k16.row.col.f32.f16.f16.f32 "
        "{%0,%1,%2,%3}, {%4,%5,%6,%7}, {%8,%9}, {%0,%1,%2,%3};\n"
        : "+f"(c[0]), "+f"(c[1]), "+f"(c[2]), "+f"(c[3])
        : "r"(a[0]), "r"(a[1]), "r"(a[2]), "r"(a[3]), "r"(b0), "r"(b1));
}
__device__ __forceinline__ void ldsm4(uint32_t (&r)[4], uint32_t addr) {
    asm volatile("ldmatrix.sync.aligned.m8n8.x4.shared.b16 {%0,%1,%2,%3}, [%4];"
                 : "=r"(r[0]), "=r"(r[1]), "=r"(r[2]), "=r"(r[3]) : "r"(addr));
}
__device__ __forceinline__ void cp_async16(uint32_t dst, const void* src) {
    asm volatile("cp.async.cg.shared.global [%0], [%1], 16;\n" :: "r"(dst), "l"(src) : "memory");
}
__device__ __forceinline__ void cp_commit() {
    asm volatile("cp.async.commit_group;\n" ::: "memory");
}
__device__ __forceinline__ uint32_t cvt_f16x2(float a, float b) {  // pack (a lo, b hi)
    uint32_t r;
    asm("cvt.rn.f16x2.f32 %0, %1, %2;" : "=r"(r) : "f"(b), "f"(a));
    return r;
}
__device__ __forceinline__ float ex2f(float x) {
    float y;
    asm("ex2.approx.ftz.f32 %0, %1;" : "=f"(y) : "f"(x));
    return y;
}

// ---------------------------------------------------------------- fused prep + QKV GEMM
// Phase 0 (CTAs 0..191): transpose/convert one 32k x 64z tile of W into g_Wt.
// Epoch grid-barrier (all 256 CTAs co-resident: occ 2 x 148 SM = 296 slots).
// Phase 1: BK=64 GEMM, triple-buffered W, double-buffered X.
__global__ void __launch_bounds__(256, 2)
qkv_gemm(const float* __restrict__ X,
         const float* __restrict__ Wq,
         const float* __restrict__ Wk,
         const float* __restrict__ Wv) {
    extern __shared__ __half smem[];
    const uint32_t sbase = (uint32_t)__cvta_generic_to_shared(smem);
    const int tid  = threadIdx.x;

    // ---------------- phase 0: W prep (v2 tile transpose, smem reused) ----
    if (blockIdx.x < 192) {
        float* sF = reinterpret_cast<float*>(smem);      // [32][65]
        const int m  = blockIdx.x / 64;
        const int k0 = (blockIdx.x % 64) * 32;
        const float* W = (m == 0) ? Wq : ((m == 1) ? Wk : Wv);
#pragma unroll
        for (int i2 = 0; i2 < 2; i2++) {
            int u = tid + i2 * 256;                      // float4 index
            int kl = u >> 4, c4 = u & 15;
            float4 v = reinterpret_cast<const float4*>(
                W + (size_t)(k0 + kl) * 64)[c4];
            sF[kl * 65 + c4 * 4 + 0] = v.x;
            sF[kl * 65 + c4 * 4 + 1] = v.y;
            sF[kl * 65 + c4 * 4 + 2] = v.z;
            sF[kl * 65 + c4 * 4 + 3] = v.w;
        }
        __syncthreads();
        const int z   = tid >> 2;
        const int klq = (tid & 3) * 8;
        uint32_t p[4];
#pragma unroll
        for (int j = 0; j < 4; j++)
            p[j] = cvt_f16x2(sF[(klq + 2 * j) * 65 + z],
                             sF[(klq + 2 * j + 1) * 65 + z]);
        size_t o = (size_t)(m * 64 + z) * KDIM + k0 + klq;
        *reinterpret_cast<uint4*>(&g_Wt[o]) = make_uint4(p[0], p[1], p[2], p[3]);
    }

    // ---------------- epoch grid-barrier (monotonic; graph-replay safe) ---
    __threadfence();
    __syncthreads();
    if (tid == 0) {
        unsigned old = atomicAdd(&g_count, 1u);
        unsigned target = (old & ~(unsigned)(NCTA - 1)) + (unsigned)NCTA;
        unsigned v;
        do {
            asm volatile("ld.acquire.gpu.global.u32 %0, [%1];"
                         : "=r"(v) : "l"(&g_count));
        } while (v < target);
    }
    __syncthreads();

    // ---------------- phase 1: GEMM -------------------------------------
    const int lane = tid & 31;
    const int wid  = tid >> 5;
    const int g    = lane >> 2;
    const int tig  = lane & 3;
    const int warp_m = (wid & 1) * 32;     // 2 warp rows of 32
    const int warp_n = (wid >> 1) * 48;    // 4 warp cols of 48
    const int m0 = blockIdx.x * BM;

    const int lrow = lane & 7;
    const int lbit3 = (lane >> 3) & 1;
    const int lbit4 = (lane >> 4) & 1;

    uint32_t aA[2];
#pragma unroll
    for (int mt = 0; mt < 2; mt++) {
        int row = warp_m + mt * 16 + lrow + lbit3 * 8;
        aA[mt] = sbase + OFF_X_B + (uint32_t)row * 144u + (uint32_t)lbit4 * 16u;
    }
    uint32_t bA[3];
#pragma unroll
    for (int p = 0; p < 3; p++) {
        int row = warp_n + p * 16 + lrow + lbit4 * 8;
        bA[p] = sbase + OFF_W_B + (uint32_t)row * 144u + (uint32_t)lbit3 * 16u;
    }

    // X: 4 threads/row
    const int xr = tid >> 2;               // 0..63
    const int xq = tid & 3;
    const uint32_t xsts = sbase + OFF_X_B + (uint32_t)xr * 144u + (uint32_t)xq * 16u;
    const float* xsrc_row = X + (size_t)(m0 + xr) * KDIM + xq * 8;

    const uint32_t wdst0 = sbase + OFF_W_B;

    float acc[2][6][4];
#pragma unroll
    for (int mt = 0; mt < 2; mt++)
#pragma unroll
        for (int nt = 0; nt < 6; nt++)
#pragma unroll
            for (int r = 0; r < 4; r++) acc[mt][nt][r] = 0.f;

    float4 xf[2];

    auto convert_sts = [&](uint32_t dOff, int h) {
        uint32_t hw[4];
        hw[0] = cvt_f16x2(xf[0].x, xf[0].y);
        hw[1] = cvt_f16x2(xf[0].z, xf[0].w);
        hw[2] = cvt_f16x2(xf[1].x, xf[1].y);
        hw[3] = cvt_f16x2(xf[1].z, xf[1].w);
        asm volatile("st.shared.v4.b32 [%0], {%1,%2,%3,%4};" ::
                     "r"(xsts + dOff + (uint32_t)h * 64u),
                     "r"(hw[0]), "r"(hw[1]), "r"(hw[2]), "r"(hw[3]));
    };

    auto ldg_x = [&](int c, int h) {
        const float4* p = reinterpret_cast<const float4*>(
            xsrc_row + (size_t)c * BK + h * 32);
        xf[0] = p[0]; xf[1] = p[1];
    };

    auto issue_w = [&](int c, uint32_t dOff) {
        const size_t koff = (size_t)c * BK;
#pragma unroll
        for (int r = 0; r < 6; r++) {
            int u = tid + r * 256;
            int n = u >> 3, q = u & 7;
            uint32_t d = wdst0 + dOff + (uint32_t)n * 144u + (uint32_t)q * 16u;
            cp_async16(d, g_Wt + (size_t)n * KDIM + koff + q * 8);
        }
        cp_commit();
    };

    // --- prologue ---
    issue_w(0, 0);
    issue_w(1, WBUF_STRIDE_B);
    ldg_x(0, 0); convert_sts(0, 0);
    ldg_x(0, 1); convert_sts(0, 1);
    ldg_x(1, 0);
    asm volatile("cp.async.wait_group 1;\n" ::: "memory");   // W(0) landed
    __syncthreads();

    uint32_t wCur = 0, wNext = WBUF_STRIDE_B, wFill = 2u * WBUF_STRIDE_B;

#pragma unroll 1
    for (int c = 0; c < NCHUNK; ++c) {
        const uint32_t xOff  = (uint32_t)(c & 1) * XBUF_STRIDE_B;
        const uint32_t xNext = (uint32_t)((c + 1) & 1) * XBUF_STRIDE_B;

        if (c + 1 < NCHUNK) {
            convert_sts(xNext, 0);
            ldg_x(c + 1, 1);
        }
        if (c + 2 < NCHUNK) issue_w(c + 2, wFill);

#pragma unroll
        for (int kk2 = 0; kk2 < 2; kk2++) {
            const uint32_t kb = kk2 * 32;
            uint32_t ah[2][4], bh[3][4];
#pragma unroll
            for (int mt = 0; mt < 2; mt++) ldsm4(ah[mt], aA[mt] + xOff + kb);
#pragma unroll
            for (int p = 0; p < 3; p++)    ldsm4(bh[p], bA[p] + wCur + kb);
#pragma unroll
            for (int mt = 0; mt < 2; mt++)
#pragma unroll
                for (int nt = 0; nt < 6; nt++)
                    mma16816(acc[mt][nt], ah[mt],
                             bh[nt >> 1][(nt & 1) * 2], bh[nt >> 1][(nt & 1) * 2 + 1]);
        }

        if (c + 1 < NCHUNK) {
            convert_sts(xNext, 1);
            if (c + 2 < NCHUNK) ldg_x(c + 2, 0);
        }

#pragma unroll
        for (int kk2 = 2; kk2 < 4; kk2++) {
            const uint32_t kb = kk2 * 32;
            uint32_t ah[2][4], bh[3][4];
#pragma unroll
            for (int mt = 0; mt < 2; mt++) ldsm4(ah[mt], aA[mt] + xOff + kb);
#pragma unroll
            for (int p = 0; p < 3; p++)    ldsm4(bh[p], bA[p] + wCur + kb);
#pragma unroll
            for (int mt = 0; mt < 2; mt++)
#pragma unroll
                for (int nt = 0; nt < 6; nt++)
                    mma16816(acc[mt][nt], ah[mt],
                             bh[nt >> 1][(nt & 1) * 2], bh[nt >> 1][(nt & 1) * 2 + 1]);
        }

        if (c + 1 < NCHUNK) {
            if (c + 2 < NCHUNK) {
                asm volatile("cp.async.wait_group 1;\n" ::: "memory");
            } else {
                asm volatile("cp.async.wait_group 0;\n" ::: "memory");
            }
            __syncthreads();
        }

        uint32_t tmp = wCur; wCur = wNext; wNext = wFill; wFill = tmp;
    }

    // epilogue: write q|k|v to scratch
#pragma unroll
    for (int mt = 0; mt < 2; mt++) {
#pragma unroll
        for (int nt = 0; nt < 6; nt++) {
            int r  = m0 + warp_m + mt * 16 + g;
            int cn = warp_n + nt * 8 + 2 * tig;
            float2 v0 = make_float2(acc[mt][nt][0], acc[mt][nt][1]);
            float2 v1 = make_float2(acc[mt][nt][2], acc[mt][nt][3]);
            *reinterpret_cast<float2*>(&g_qkv[(size_t)r * NTOT + cn]) = v0;
            *reinterpret_cast<float2*>(&g_qkv[(size_t)(r + 8) * NTOT + cn]) = v1;
        }
    }
}

// ---------------------------------------------------------------- attention
// No max-subtraction (softmax shift-invariant; |q·k| within fp32 exp range).
__global__ void __launch_bounds__(256)
attn_kernel(float* __restrict__ out) {
    __shared__ float4 ks[4][16];
    __shared__ float4 vs[4][16];
    const int tid = threadIdx.x;
    const int tl = tid >> 6;
    const int i  = tid & 63;
    const size_t tok = (size_t)blockIdx.x * 4 + tl;
    const float* base = g_qkv + tok * NTOT;

    float q = base[i] * 1.4426950408889634f;   // fold log2(e)
    reinterpret_cast<float*>(&ks[tl][0])[i] = base[64 + i];
    reinterpret_cast<float*>(&vs[tl][0])[i] = base[128 + i];
    __syncthreads();

    float s = 0.f, num = 0.f;
#pragma unroll
    for (int j4 = 0; j4 < 16; j4++) {
        float4 k4 = ks[tl][j4];
        float4 v4 = vs[tl][j4];
        float e0 = ex2f(q * k4.x);
        float e1 = ex2f(q * k4.y);
        float e2 = ex2f(q * k4.z);
        float e3 = ex2f(q * k4.w);
        s += (e0 + e1) + (e2 + e3);
        num = fmaf(e0, v4.x, num);
        num = fmaf(e1, v4.y, num);
        num = fmaf(e2, v4.z, num);
        num = fmaf(e3, v4.w, num);
    }
    out[tok * 64 + i] = num / s;
}

// ----------------------------------------------------------------
extern "C" void kernel_launch(void* const* d_in, const int* in_sizes, int n_in,
                              void* d_out, int out_size) {
    const float* X  = (const float*)d_in[0];
    const float* Wq = (const float*)d_in[1];
    const float* Wk = (const float*)d_in[2];
    const float* Wv = (const float*)d_in[3];
    float* out = (float*)d_out;

    cudaFuncSetAttribute(qkv_gemm, cudaFuncAttributeMaxDynamicSharedMemorySize,
                         SMEM_BYTES);

    qkv_gemm<<<NCTA, 256, SMEM_BYTES>>>(X, Wq, Wk, Wv);
    attn_kernel<<<M_TOK / 4, 256>>>(out);
}